// round 1
// baseline (speedup 1.0000x reference)
#include <cuda_runtime.h>
#include <cstdint>

// Problem constants
#define SS     512
#define BB     32
#define HH     512
#define NSPAN  2048
#define DD     256
#define LMAXC  16
#define LDIMC  32
#define VV     50257
#define KP     2080          // phrase concat width: 32 + 4*512
#define KC     1056          // context concat width: 32 + 2*512
#define NROWS  4096          // 2*NSPAN
#define BN_V   128
#define NTV    393           // ceil(50257/128)
#define NEG_BIG -1e30f

// Scratch (no allocs allowed): ~35 MB of device globals
__device__ float g_X[NSPAN * KP];          // gathered phrase features [N, 2080]
__device__ float g_feats[NROWS * DD];      // ctx rows 0..N-1, phr rows N..2N-1
__device__ float g_pm[NROWS * NTV];        // per (row, vtile) partial max
__device__ float g_ps[NROWS * NTV];        // per (row, vtile) partial sumexp
__device__ float g_focal[NROWS];           // per-row focal term

// ---------------------------------------------------------------------------
// 1) Gather span features into X_phr [N, 2080] = [le, f_b, f_e, b_e, b_b]
// ---------------------------------------------------------------------------
__global__ void gather_kernel(const float* __restrict__ fwd,
                              const float* __restrict__ bwd,
                              const int* __restrict__ begins,
                              const int* __restrict__ ends,
                              const int* __restrict__ bids,
                              const float* __restrict__ len_emb) {
    int n = blockIdx.x;
    int t = threadIdx.x;                 // 256 threads
    int b  = bids[n];
    int bg = begins[n];
    int en = ends[n];
    int len = min(en - bg, LMAXC) - 1;

    float* X = g_X + n * KP;
    if (t < LDIMC) X[t] = len_emb[len * LDIMC + t];

    const float* fb = fwd + ((size_t)(bg - 1) * BB + b) * HH;
    const float* fe = fwd + ((size_t)(en - 1) * BB + b) * HH;
    const float* be = bwd + ((size_t)en * BB + b) * HH;
    const float* bb = bwd + ((size_t)bg * BB + b) * HH;
    for (int h = t; h < HH; h += 256) {
        X[LDIMC + h]             = fb[h];
        X[LDIMC + 512 + h]       = fe[h];
        X[LDIMC + 1024 + h]      = be[h];
        X[LDIMC + 1536 + h]      = bb[h];
    }
}

// ---------------------------------------------------------------------------
// 2) Feature GEMMs: Y[n][d] = tanh(b[d] + sum_k X[n, map(k)] * W[d][k])
//    ctx map: k<544 -> k ; k>=544 -> k+512 (b_e lives at phr offset 1056)
//    Tile 64x64, BK=16, 256 threads, 4x4 microtile.
// ---------------------------------------------------------------------------
template <int KTOT, bool IS_CTX>
__global__ __launch_bounds__(256) void feat_gemm(const float* __restrict__ W,
                                                 const float* __restrict__ bias,
                                                 int row_offset) {
    __shared__ float As[16][68];
    __shared__ float Bs[16][68];
    int tid = threadIdx.x;
    int ty = tid >> 4, tx = tid & 15;
    int rb = blockIdx.y * 64;     // span base
    int cb = blockIdx.x * 64;     // d base
    int lrow = tid >> 2, lq = tid & 3;

    float acc[4][4] = {};

    for (int k0 = 0; k0 < KTOT; k0 += 16) {
        int kk = k0 + lq * 4;
        int xk = IS_CTX ? (kk < 544 ? kk : kk + 512) : kk;
        float4 av = *(const float4*)&g_X[(rb + lrow) * KP + xk];
        As[lq * 4 + 0][lrow] = av.x;
        As[lq * 4 + 1][lrow] = av.y;
        As[lq * 4 + 2][lrow] = av.z;
        As[lq * 4 + 3][lrow] = av.w;
        float4 bv = *(const float4*)&W[(size_t)(cb + lrow) * KTOT + kk];
        Bs[lq * 4 + 0][lrow] = bv.x;
        Bs[lq * 4 + 1][lrow] = bv.y;
        Bs[lq * 4 + 2][lrow] = bv.z;
        Bs[lq * 4 + 3][lrow] = bv.w;
        __syncthreads();
#pragma unroll
        for (int k = 0; k < 16; k++) {
            float a[4], b[4];
#pragma unroll
            for (int i = 0; i < 4; i++) a[i] = As[k][ty * 4 + i];
#pragma unroll
            for (int j = 0; j < 4; j++) b[j] = Bs[k][tx * 4 + j];
#pragma unroll
            for (int i = 0; i < 4; i++)
#pragma unroll
                for (int j = 0; j < 4; j++) acc[i][j] += a[i] * b[j];
        }
        __syncthreads();
    }

#pragma unroll
    for (int i = 0; i < 4; i++) {
        int r = row_offset + rb + ty * 4 + i;
#pragma unroll
        for (int j = 0; j < 4; j++) {
            int d = cb + tx * 4 + j;
            g_feats[r * DD + d] = tanhf(acc[i][j] + bias[d]);
        }
    }
}

// ---------------------------------------------------------------------------
// 3) Big GEMM + fused per-tile softmax partials.
//    C[r][v] = feats[r] . W_lab[v] + b_lab[v], tile 128x128, K=256, BK=16,
//    256 threads, 8x8 microtile. Epilogue: per-row (max, sumexp) over the
//    128-col tile (invalid v >= V masked to -1e30), written to g_pm/g_ps.
// ---------------------------------------------------------------------------
__global__ __launch_bounds__(256, 1) void big_gemm(const float* __restrict__ Wlab,
                                                   const float* __restrict__ blab) {
    __shared__ float As[16][132];
    __shared__ float Bs[16][132];
    __shared__ float red[128][17];
    __shared__ float rowm[128];

    int tid = threadIdx.x;
    int ty = tid >> 4, tx = tid & 15;
    int rb = blockIdx.y * 128;
    int vb = blockIdx.x * BN_V;
    int lrow = tid >> 2, lq = tid & 3;

    float acc[8][8] = {};

    for (int k0 = 0; k0 < 256; k0 += 16) {
#pragma unroll
        for (int p = 0; p < 2; p++) {
            int r = lrow + p * 64;
            float4 av = *(const float4*)&g_feats[(rb + r) * DD + k0 + lq * 4];
            As[lq * 4 + 0][r] = av.x;
            As[lq * 4 + 1][r] = av.y;
            As[lq * 4 + 2][r] = av.z;
            As[lq * 4 + 3][r] = av.w;
            int v = vb + r;
            float4 bv = make_float4(0.f, 0.f, 0.f, 0.f);
            if (v < VV) bv = *(const float4*)&Wlab[(size_t)v * DD + k0 + lq * 4];
            Bs[lq * 4 + 0][r] = bv.x;
            Bs[lq * 4 + 1][r] = bv.y;
            Bs[lq * 4 + 2][r] = bv.z;
            Bs[lq * 4 + 3][r] = bv.w;
        }
        __syncthreads();
#pragma unroll
        for (int k = 0; k < 16; k++) {
            float4 a0 = *(const float4*)&As[k][ty * 8];
            float4 a1 = *(const float4*)&As[k][ty * 8 + 4];
            float4 b0 = *(const float4*)&Bs[k][tx * 8];
            float4 b1 = *(const float4*)&Bs[k][tx * 8 + 4];
            float a[8] = {a0.x, a0.y, a0.z, a0.w, a1.x, a1.y, a1.z, a1.w};
            float b[8] = {b0.x, b0.y, b0.z, b0.w, b1.x, b1.y, b1.z, b1.w};
#pragma unroll
            for (int i = 0; i < 8; i++)
#pragma unroll
                for (int j = 0; j < 8; j++) acc[i][j] += a[i] * b[j];
        }
        __syncthreads();
    }

    // --- fused softmax-partial epilogue ---
    // add bias, mask invalid v, per-thread row max over 8 cols
#pragma unroll
    for (int i = 0; i < 8; i++) {
        float mx = NEG_BIG;
#pragma unroll
        for (int j = 0; j < 8; j++) {
            int v = vb + tx * 8 + j;
            float val = (v < VV) ? (acc[i][j] + blab[v]) : NEG_BIG;
            acc[i][j] = val;
            mx = fmaxf(mx, val);
        }
        red[ty * 8 + i][tx] = mx;
    }
    __syncthreads();
    if (tid < 128) {
        float m = NEG_BIG;
#pragma unroll
        for (int t = 0; t < 16; t++) m = fmaxf(m, red[tid][t]);
        rowm[tid] = m;
    }
    __syncthreads();
#pragma unroll
    for (int i = 0; i < 8; i++) {
        float m = rowm[ty * 8 + i];
        float s = 0.f;
#pragma unroll
        for (int j = 0; j < 8; j++) s += __expf(acc[i][j] - m);
        red[ty * 8 + i][tx] = s;
    }
    __syncthreads();
    if (tid < 128) {
        float s = 0.f;
#pragma unroll
        for (int t = 0; t < 16; t++) s += red[tid][t];
        int r = rb + tid;
        g_pm[r * NTV + blockIdx.x] = rowm[tid];
        g_ps[r * NTV + blockIdx.x] = s;
    }
}

// ---------------------------------------------------------------------------
// 4) Per-row reduction: combine 393 (m,s) partials -> lse, compute target
//    logit via a 256-dot, then the focal term. One warp per row.
// ---------------------------------------------------------------------------
__global__ void row_reduce(const float* __restrict__ Wlab,
                           const float* __restrict__ blab,
                           const int* __restrict__ tags) {
    int warp = (blockIdx.x * blockDim.x + threadIdx.x) >> 5;
    int lane = threadIdx.x & 31;
    if (warp >= NROWS) return;
    int r = warp;

    float m = NEG_BIG, s = 0.f;
    for (int t = lane; t < NTV; t += 32) {
        float mt = g_pm[r * NTV + t];
        float st = g_ps[r * NTV + t];
        if (mt > m) { s = s * __expf(m - mt) + st; m = mt; }
        else        { s += st * __expf(mt - m); }
    }
#pragma unroll
    for (int o = 16; o > 0; o >>= 1) {
        float mo = __shfl_xor_sync(0xffffffffu, m, o);
        float so = __shfl_xor_sync(0xffffffffu, s, o);
        if (mo > m) { s = s * __expf(m - mo) + so; m = mo; }
        else        { s += so * __expf(mo - m); }
    }
    float lse = m + __logf(s);

    int tag = tags[r & (NSPAN - 1)];
    const float* fr = g_feats + r * DD;
    const float* wr = Wlab + (size_t)tag * DD;
    float dot = 0.f;
    for (int d = lane; d < DD; d += 32) dot += fr[d] * wr[d];
#pragma unroll
    for (int o = 16; o > 0; o >>= 1) dot += __shfl_xor_sync(0xffffffffu, dot, o);

    if (lane == 0) {
        float lp = dot + blab[tag] - lse;
        float p = __expf(lp);
        float om = 1.f - p;
        g_focal[r] = -om * om * lp;   // GAMMA = 2
    }
}

// ---------------------------------------------------------------------------
// 5) Deterministic final sum (single CTA; no atomics -> graph-replay stable)
// ---------------------------------------------------------------------------
__global__ void final_reduce(float* __restrict__ out) {
    __shared__ float sm[1024];
    int t = threadIdx.x;
    float s = 0.f;
    for (int i = t; i < NROWS; i += 1024) s += g_focal[i];
    sm[t] = s;
    __syncthreads();
    for (int o = 512; o > 0; o >>= 1) {
        if (t < o) sm[t] += sm[t + o];
        __syncthreads();
    }
    if (t == 0) out[0] = sm[0] / ((float)NROWS + 1e-5f);
}

// ---------------------------------------------------------------------------
extern "C" void kernel_launch(void* const* d_in, const int* in_sizes, int n_in,
                              void* d_out, int out_size) {
    const float* fwd     = (const float*)d_in[0];
    const float* bwd     = (const float*)d_in[1];
    const int*   begins  = (const int*)  d_in[2];
    const int*   ends    = (const int*)  d_in[3];
    const int*   bids    = (const int*)  d_in[4];
    const int*   tags    = (const int*)  d_in[5];
    const float* len_emb = (const float*)d_in[6];
    const float* W_ctx   = (const float*)d_in[7];
    const float* b_ctx   = (const float*)d_in[8];
    const float* W_phr   = (const float*)d_in[9];
    const float* b_phr   = (const float*)d_in[10];
    const float* W_lab   = (const float*)d_in[11];
    const float* b_lab   = (const float*)d_in[12];
    float* out = (float*)d_out;

    gather_kernel<<<NSPAN, 256>>>(fwd, bwd, begins, ends, bids, len_emb);
    feat_gemm<KC, true ><<<dim3(4, 32), 256>>>(W_ctx, b_ctx, 0);
    feat_gemm<KP, false><<<dim3(4, 32), 256>>>(W_phr, b_phr, NSPAN);
    big_gemm<<<dim3(NTV, 32), 256>>>(W_lab, b_lab);
    row_reduce<<<512, 256>>>(W_lab, b_lab, tags);
    final_reduce<<<1, 1024>>>(out);
}

// round 3
// speedup vs baseline: 3.9540x; 3.9540x over previous
#include <cuda_runtime.h>
#include <cuda_bf16.h>
#include <cstdint>

// Problem constants
#define SS     512
#define BB     32
#define HH     512
#define NSPAN  2048
#define DD     256
#define LMAXC  16
#define LDIMC  32
#define VV     50257
#define KP     2080
#define KC     1056
#define NROWS  4096
#define NTV    393            // ceil(50257/128) vocab tiles
#define NVPAD  (NTV*128)      // 50304 padded vocab rows
#define NEG_BIG -1e30f

// ---------------- scratch (device globals; no allocs allowed) ----------------
__device__ float g_X[NSPAN * KP];
__device__ float g_feats[NROWS * DD];
__device__ __align__(16) __nv_bfloat16 g_Ab[NROWS * DD];        // bf16 feats, row-major
__device__ __align__(16) __nv_bfloat16 g_Wb[(size_t)NVPAD * DD];// bf16 W_lab, row-major, zero-padded
__device__ float g_pm[NROWS * NTV];
__device__ float g_ps[NROWS * NTV];
__device__ float g_focal[NROWS];

// ---------------------------------------------------------------------------
// 1) Gather span features into X_phr [N, 2080] = [le, f_b, f_e, b_e, b_b]
// ---------------------------------------------------------------------------
__global__ void gather_kernel(const float* __restrict__ fwd,
                              const float* __restrict__ bwd,
                              const int* __restrict__ begins,
                              const int* __restrict__ ends,
                              const int* __restrict__ bids,
                              const float* __restrict__ len_emb) {
    int n = blockIdx.x;
    int t = threadIdx.x;
    int b = bids[n], bg = begins[n], en = ends[n];
    int len = min(en - bg, LMAXC) - 1;
    float* X = g_X + n * KP;
    if (t < LDIMC) X[t] = len_emb[len * LDIMC + t];
    const float* fb = fwd + ((size_t)(bg - 1) * BB + b) * HH;
    const float* fe = fwd + ((size_t)(en - 1) * BB + b) * HH;
    const float* be = bwd + ((size_t)en * BB + b) * HH;
    const float* bb = bwd + ((size_t)bg * BB + b) * HH;
    for (int h = t; h < HH; h += 256) {
        X[LDIMC + h]        = fb[h];
        X[LDIMC + 512 + h]  = fe[h];
        X[LDIMC + 1024 + h] = be[h];
        X[LDIMC + 1536 + h] = bb[h];
    }
}

// ---------------------------------------------------------------------------
// 2) Feature GEMMs: fp32; epilogue writes fp32 g_feats AND bf16 g_Ab
// ---------------------------------------------------------------------------
template <int KTOT, bool IS_CTX>
__global__ __launch_bounds__(256) void feat_gemm(const float* __restrict__ W,
                                                 const float* __restrict__ bias,
                                                 int row_offset) {
    __shared__ float As[16][68];
    __shared__ float Bs[16][68];
    int tid = threadIdx.x;
    int ty = tid >> 4, tx = tid & 15;
    int rb = blockIdx.y * 64;
    int cb = blockIdx.x * 64;
    int lrow = tid >> 2, lq = tid & 3;

    float acc[4][4] = {};
    for (int k0 = 0; k0 < KTOT; k0 += 16) {
        int kk = k0 + lq * 4;
        int xk = IS_CTX ? (kk < 544 ? kk : kk + 512) : kk;
        float4 av = *(const float4*)&g_X[(rb + lrow) * KP + xk];
        As[lq * 4 + 0][lrow] = av.x; As[lq * 4 + 1][lrow] = av.y;
        As[lq * 4 + 2][lrow] = av.z; As[lq * 4 + 3][lrow] = av.w;
        float4 bv = *(const float4*)&W[(size_t)(cb + lrow) * KTOT + kk];
        Bs[lq * 4 + 0][lrow] = bv.x; Bs[lq * 4 + 1][lrow] = bv.y;
        Bs[lq * 4 + 2][lrow] = bv.z; Bs[lq * 4 + 3][lrow] = bv.w;
        __syncthreads();
#pragma unroll
        for (int k = 0; k < 16; k++) {
            float a[4], b[4];
#pragma unroll
            for (int i = 0; i < 4; i++) a[i] = As[k][ty * 4 + i];
#pragma unroll
            for (int j = 0; j < 4; j++) b[j] = Bs[k][tx * 4 + j];
#pragma unroll
            for (int i = 0; i < 4; i++)
#pragma unroll
                for (int j = 0; j < 4; j++) acc[i][j] += a[i] * b[j];
        }
        __syncthreads();
    }

#pragma unroll
    for (int i = 0; i < 4; i++) {
        int r = row_offset + rb + ty * 4 + i;
        int d0 = cb + tx * 4;
        float t0 = tanhf(acc[i][0] + bias[d0 + 0]);
        float t1 = tanhf(acc[i][1] + bias[d0 + 1]);
        float t2 = tanhf(acc[i][2] + bias[d0 + 2]);
        float t3 = tanhf(acc[i][3] + bias[d0 + 3]);
        float* fr = g_feats + r * DD + d0;
        fr[0] = t0; fr[1] = t1; fr[2] = t2; fr[3] = t3;
        __nv_bfloat162 h0 = __floats2bfloat162_rn(t0, t1);
        __nv_bfloat162 h1 = __floats2bfloat162_rn(t2, t3);
        uint2 w;
        w.x = *(uint32_t*)&h0; w.y = *(uint32_t*)&h1;
        *(uint2*)&g_Ab[r * DD + d0] = w;
    }
}

// ---------------------------------------------------------------------------
// 3) Convert W_lab fp32 -> bf16 row-major (pad rows >= VV with zeros)
// ---------------------------------------------------------------------------
__global__ __launch_bounds__(256) void convert_wlab(const float* __restrict__ W) {
    int idx = blockIdx.x * 256 + threadIdx.x;   // NVPAD*32 threads total
    int rg = idx >> 5;
    int kc = (idx & 31) << 3;
    if (rg >= NVPAD) return;
    float4 w0 = make_float4(0.f, 0.f, 0.f, 0.f), w1 = w0;
    if (rg < VV) {
        const float4* p = (const float4*)(W + (size_t)rg * DD + kc);
        w0 = p[0]; w1 = p[1];
    }
    __nv_bfloat162 h0 = __floats2bfloat162_rn(w0.x, w0.y);
    __nv_bfloat162 h1 = __floats2bfloat162_rn(w0.z, w0.w);
    __nv_bfloat162 h2 = __floats2bfloat162_rn(w1.x, w1.y);
    __nv_bfloat162 h3 = __floats2bfloat162_rn(w1.z, w1.w);
    uint4 u;
    u.x = *(uint32_t*)&h0; u.y = *(uint32_t*)&h1;
    u.z = *(uint32_t*)&h2; u.w = *(uint32_t*)&h3;
    *(uint4*)&g_Wb[(size_t)rg * DD + kc] = u;
}

// ---------------------------------------------------------------------------
// 4) bf16 mma.sync GEMM + fused softmax partials.
//    CTA: 128 rows x 128 vocab, K=256 (8 x BK=32). 8 warps (2x4), warp 64x32.
// ---------------------------------------------------------------------------
#define APITCH 20   // uint32 words per smem row (32 halves=16 words + pad, 16B-aligned)

__device__ __forceinline__ void mma16816(float* c, uint32_t a0, uint32_t a1,
                                         uint32_t a2, uint32_t a3,
                                         uint32_t b0, uint32_t b1) {
    asm volatile("mma.sync.aligned.m16n8k16.row.col.f32.bf16.bf16.f32 "
        "{%0,%1,%2,%3}, {%4,%5,%6,%7}, {%8,%9}, {%0,%1,%2,%3};"
        : "+f"(c[0]), "+f"(c[1]), "+f"(c[2]), "+f"(c[3])
        : "r"(a0), "r"(a1), "r"(a2), "r"(a3), "r"(b0), "r"(b1));
}

__global__ void __launch_bounds__(256) big_gemm_mma(const float* __restrict__ blab) {
    __shared__ uint32_t As[128][APITCH];
    __shared__ uint32_t Bs[128][APITCH];
    __shared__ float pm_s[128][4];
    __shared__ float ps_s[128][4];
    __shared__ float bias_s[128];

    int tid  = threadIdx.x;
    int wid  = tid >> 5, lane = tid & 31;
    int g    = lane >> 2, t4 = lane & 3;
    int wr   = wid >> 2, wc = wid & 3;        // warp grid 2 x 4
    int vt   = blockIdx.x, rt = blockIdx.y;
    int vb   = vt * 128;

    if (tid < 128) {
        int v = vb + tid;
        bias_s[tid] = (v < VV) ? blab[v] : 0.f;
    }

    const uint4* gA = (const uint4*)(g_Ab + (size_t)rt * 128 * DD);
    const uint4* gB = (const uint4*)(g_Wb + (size_t)vb * DD);
    int lr = tid >> 1;            // smem row this thread fills
    int cc = (tid & 1) * 2;       // uint4 chunk base within the 4-chunk row slice

    float acc[4][4][4] = {};      // [mt][nt][c0..c3]

    uint4 pa0 = gA[lr * 16 + cc], pa1 = gA[lr * 16 + cc + 1];
    uint4 pb0 = gB[lr * 16 + cc], pb1 = gB[lr * 16 + cc + 1];

    for (int it = 0; it < 8; it++) {
        *(uint4*)&As[lr][cc * 4]     = pa0;
        *(uint4*)&As[lr][cc * 4 + 4] = pa1;
        *(uint4*)&Bs[lr][cc * 4]     = pb0;
        *(uint4*)&Bs[lr][cc * 4 + 4] = pb1;
        __syncthreads();
        if (it < 7) {
            int base = lr * 16 + (it + 1) * 4 + cc;
            pa0 = gA[base]; pa1 = gA[base + 1];
            pb0 = gB[base]; pb1 = gB[base + 1];
        }
#pragma unroll
        for (int ks = 0; ks < 2; ks++) {
            int w0 = ks * 8 + t4;
            int w1 = w0 + 4;
            uint32_t af[4][4], bf[4][2];
#pragma unroll
            for (int mt = 0; mt < 4; mt++) {
                int m = wr * 64 + mt * 16 + g;
                af[mt][0] = As[m][w0];
                af[mt][1] = As[m + 8][w0];
                af[mt][2] = As[m][w1];
                af[mt][3] = As[m + 8][w1];
            }
#pragma unroll
            for (int nt = 0; nt < 4; nt++) {
                int n = wc * 32 + nt * 8 + g;
                bf[nt][0] = Bs[n][w0];
                bf[nt][1] = Bs[n][w1];
            }
#pragma unroll
            for (int mt = 0; mt < 4; mt++)
#pragma unroll
                for (int nt = 0; nt < 4; nt++)
                    mma16816(acc[mt][nt], af[mt][0], af[mt][1], af[mt][2], af[mt][3],
                             bf[nt][0], bf[nt][1]);
        }
        __syncthreads();
    }

    // --- fused softmax-partial epilogue (register + quad-shuffle) ---
#pragma unroll
    for (int mt = 0; mt < 4; mt++) {
#pragma unroll
        for (int h = 0; h < 2; h++) {
            int rl = wr * 64 + mt * 16 + h * 8 + g;
            float v[8];
#pragma unroll
            for (int nt = 0; nt < 4; nt++) {
                int col = wc * 32 + nt * 8 + t4 * 2;
                float v0 = acc[mt][nt][h * 2 + 0] + bias_s[col];
                float v1 = acc[mt][nt][h * 2 + 1] + bias_s[col + 1];
                if (vb + col     >= VV) v0 = NEG_BIG;
                if (vb + col + 1 >= VV) v1 = NEG_BIG;
                v[nt * 2 + 0] = v0; v[nt * 2 + 1] = v1;
            }
            float mx = v[0];
#pragma unroll
            for (int j = 1; j < 8; j++) mx = fmaxf(mx, v[j]);
            mx = fmaxf(mx, __shfl_xor_sync(0xffffffffu, mx, 1));
            mx = fmaxf(mx, __shfl_xor_sync(0xffffffffu, mx, 2));
            float s = 0.f;
#pragma unroll
            for (int j = 0; j < 8; j++) s += __expf(v[j] - mx);
            s += __shfl_xor_sync(0xffffffffu, s, 1);
            s += __shfl_xor_sync(0xffffffffu, s, 2);
            if (t4 == 0) { pm_s[rl][wc] = mx; ps_s[rl][wc] = s; }
        }
    }
    __syncthreads();
    if (tid < 128) {
        float m = fmaxf(fmaxf(pm_s[tid][0], pm_s[tid][1]),
                        fmaxf(pm_s[tid][2], pm_s[tid][3]));
        float s = 0.f;
#pragma unroll
        for (int w = 0; w < 4; w++) s += ps_s[tid][w] * __expf(pm_s[tid][w] - m);
        int r = rt * 128 + tid;
        g_pm[r * NTV + vt] = m;
        g_ps[r * NTV + vt] = s;
    }
}

// ---------------------------------------------------------------------------
// 5) Per-row reduction: combine partials -> lse, target logit, focal term
// ---------------------------------------------------------------------------
__global__ void row_reduce(const float* __restrict__ Wlab,
                           const float* __restrict__ blab,
                           const int* __restrict__ tags) {
    int warp = (blockIdx.x * blockDim.x + threadIdx.x) >> 5;
    int lane = threadIdx.x & 31;
    if (warp >= NROWS) return;
    int r = warp;
    float m = NEG_BIG, s = 0.f;
    for (int t = lane; t < NTV; t += 32) {
        float mt = g_pm[r * NTV + t];
        float st = g_ps[r * NTV + t];
        if (mt > m) { s = s * __expf(m - mt) + st; m = mt; }
        else        { s += st * __expf(mt - m); }
    }
#pragma unroll
    for (int o = 16; o > 0; o >>= 1) {
        float mo = __shfl_xor_sync(0xffffffffu, m, o);
        float so = __shfl_xor_sync(0xffffffffu, s, o);
        if (mo > m) { s = s * __expf(m - mo) + so; m = mo; }
        else        { s += so * __expf(mo - m); }
    }
    float lse = m + __logf(s);

    int tag = tags[r & (NSPAN - 1)];
    const float* fr = g_feats + r * DD;
    const float* wr = Wlab + (size_t)tag * DD;
    float dot = 0.f;
    for (int d = lane; d < DD; d += 32) dot += fr[d] * wr[d];
#pragma unroll
    for (int o = 16; o > 0; o >>= 1) dot += __shfl_xor_sync(0xffffffffu, dot, o);

    if (lane == 0) {
        float lp = dot + blab[tag] - lse;
        float p = __expf(lp);
        float om = 1.f - p;
        g_focal[r] = -om * om * lp;
    }
}

// ---------------------------------------------------------------------------
// 6) Deterministic final sum
// ---------------------------------------------------------------------------
__global__ void final_reduce(float* __restrict__ out) {
    __shared__ float sm[1024];
    int t = threadIdx.x;
    float s = 0.f;
    for (int i = t; i < NROWS; i += 1024) s += g_focal[i];
    sm[t] = s;
    __syncthreads();
    for (int o = 512; o > 0; o >>= 1) {
        if (t < o) sm[t] += sm[t + o];
        __syncthreads();
    }
    if (t == 0) out[0] = sm[0] / ((float)NROWS + 1e-5f);
}

// ---------------------------------------------------------------------------
extern "C" void kernel_launch(void* const* d_in, const int* in_sizes, int n_in,
                              void* d_out, int out_size) {
    const float* fwd     = (const float*)d_in[0];
    const float* bwd     = (const float*)d_in[1];
    const int*   begins  = (const int*)  d_in[2];
    const int*   ends    = (const int*)  d_in[3];
    const int*   bids    = (const int*)  d_in[4];
    const int*   tags    = (const int*)  d_in[5];
    const float* len_emb = (const float*)d_in[6];
    const float* W_ctx   = (const float*)d_in[7];
    const float* b_ctx   = (const float*)d_in[8];
    const float* W_phr   = (const float*)d_in[9];
    const float* b_phr   = (const float*)d_in[10];
    const float* W_lab   = (const float*)d_in[11];
    const float* b_lab   = (const float*)d_in[12];
    float* out = (float*)d_out;

    gather_kernel<<<NSPAN, 256>>>(fwd, bwd, begins, ends, bids, len_emb);
    feat_gemm<KC, true ><<<dim3(4, 32), 256>>>(W_ctx, b_ctx, 0);
    feat_gemm<KP, false><<<dim3(4, 32), 256>>>(W_phr, b_phr, NSPAN);
    convert_wlab<<<(NVPAD * 32) / 256, 256>>>(W_lab);
    big_gemm_mma<<<dim3(NTV, 32), 256>>>(b_lab);
    row_reduce<<<512, 256>>>(W_lab, b_lab, tags);
    final_reduce<<<1, 1024>>>(out);
}

// round 4
// speedup vs baseline: 4.1905x; 1.0598x over previous
#include <cuda_runtime.h>
#include <cuda_bf16.h>
#include <cstdint>

// Problem constants
#define SS     512
#define BB     32
#define HH     512
#define NSPAN  2048
#define DD     256
#define LMAXC  16
#define LDIMC  32
#define VV     50257
#define KP     2080
#define KC     1056
#define NROWS  4096
#define NTV    393            // ceil(50257/128) vocab tiles
#define NVPAD  (NTV*128)      // 50304 padded vocab rows
#define NEG_BIG -1e30f

// ---------------- scratch (device globals; no allocs allowed) ----------------
__device__ float g_X[NSPAN * KP];
__device__ float g_feats[NROWS * DD];
__device__ __align__(16) __nv_bfloat16 g_Ab[NROWS * DD];         // bf16 feats, row-major
__device__ __align__(16) __nv_bfloat16 g_Wb[(size_t)NVPAD * DD]; // bf16 W_lab, padded
__device__ float g_pm[NROWS * NTV];
__device__ float g_ps[NROWS * NTV];
__device__ float g_focal[NROWS];

// ---------------------------------------------------------------------------
// 1) Gather span features into X_phr [N, 2080] = [le, f_b, f_e, b_e, b_b]
// ---------------------------------------------------------------------------
__global__ void gather_kernel(const float* __restrict__ fwd,
                              const float* __restrict__ bwd,
                              const int* __restrict__ begins,
                              const int* __restrict__ ends,
                              const int* __restrict__ bids,
                              const float* __restrict__ len_emb) {
    int n = blockIdx.x;
    int t = threadIdx.x;
    int b = bids[n], bg = begins[n], en = ends[n];
    int len = min(en - bg, LMAXC) - 1;
    float* X = g_X + n * KP;
    if (t < LDIMC) X[t] = len_emb[len * LDIMC + t];
    const float* fb = fwd + ((size_t)(bg - 1) * BB + b) * HH;
    const float* fe = fwd + ((size_t)(en - 1) * BB + b) * HH;
    const float* be = bwd + ((size_t)en * BB + b) * HH;
    const float* bb = bwd + ((size_t)bg * BB + b) * HH;
    for (int h = t; h < HH; h += 256) {
        X[LDIMC + h]        = fb[h];
        X[LDIMC + 512 + h]  = fe[h];
        X[LDIMC + 1024 + h] = be[h];
        X[LDIMC + 1536 + h] = bb[h];
    }
}

// ---------------------------------------------------------------------------
// 2) Feature GEMMs: fp32; epilogue writes fp32 g_feats AND bf16 g_Ab
// ---------------------------------------------------------------------------
template <int KTOT, bool IS_CTX>
__global__ __launch_bounds__(256) void feat_gemm(const float* __restrict__ W,
                                                 const float* __restrict__ bias,
                                                 int row_offset) {
    __shared__ float As[16][68];
    __shared__ float Bs[16][68];
    int tid = threadIdx.x;
    int ty = tid >> 4, tx = tid & 15;
    int rb = blockIdx.y * 64;
    int cb = blockIdx.x * 64;
    int lrow = tid >> 2, lq = tid & 3;

    float acc[4][4] = {};
    for (int k0 = 0; k0 < KTOT; k0 += 16) {
        int kk = k0 + lq * 4;
        int xk = IS_CTX ? (kk < 544 ? kk : kk + 512) : kk;
        float4 av = *(const float4*)&g_X[(rb + lrow) * KP + xk];
        As[lq * 4 + 0][lrow] = av.x; As[lq * 4 + 1][lrow] = av.y;
        As[lq * 4 + 2][lrow] = av.z; As[lq * 4 + 3][lrow] = av.w;
        float4 bv = *(const float4*)&W[(size_t)(cb + lrow) * KTOT + kk];
        Bs[lq * 4 + 0][lrow] = bv.x; Bs[lq * 4 + 1][lrow] = bv.y;
        Bs[lq * 4 + 2][lrow] = bv.z; Bs[lq * 4 + 3][lrow] = bv.w;
        __syncthreads();
#pragma unroll
        for (int k = 0; k < 16; k++) {
            float a[4], b[4];
#pragma unroll
            for (int i = 0; i < 4; i++) a[i] = As[k][ty * 4 + i];
#pragma unroll
            for (int j = 0; j < 4; j++) b[j] = Bs[k][tx * 4 + j];
#pragma unroll
            for (int i = 0; i < 4; i++)
#pragma unroll
                for (int j = 0; j < 4; j++) acc[i][j] += a[i] * b[j];
        }
        __syncthreads();
    }

#pragma unroll
    for (int i = 0; i < 4; i++) {
        int r = row_offset + rb + ty * 4 + i;
        int d0 = cb + tx * 4;
        float t0 = tanhf(acc[i][0] + bias[d0 + 0]);
        float t1 = tanhf(acc[i][1] + bias[d0 + 1]);
        float t2 = tanhf(acc[i][2] + bias[d0 + 2]);
        float t3 = tanhf(acc[i][3] + bias[d0 + 3]);
        float* fr = g_feats + r * DD + d0;
        fr[0] = t0; fr[1] = t1; fr[2] = t2; fr[3] = t3;
        __nv_bfloat162 h0 = __floats2bfloat162_rn(t0, t1);
        __nv_bfloat162 h1 = __floats2bfloat162_rn(t2, t3);
        uint2 w;
        w.x = *(uint32_t*)&h0; w.y = *(uint32_t*)&h1;
        *(uint2*)&g_Ab[r * DD + d0] = w;
    }
}

// ---------------------------------------------------------------------------
// 3) Convert W_lab fp32 -> bf16 row-major (pad rows >= VV with zeros)
// ---------------------------------------------------------------------------
__global__ __launch_bounds__(256) void convert_wlab(const float* __restrict__ W) {
    int idx = blockIdx.x * 256 + threadIdx.x;
    int rg = idx >> 5;
    int kc = (idx & 31) << 3;
    if (rg >= NVPAD) return;
    float4 w0 = make_float4(0.f, 0.f, 0.f, 0.f), w1 = w0;
    if (rg < VV) {
        const float4* p = (const float4*)(W + (size_t)rg * DD + kc);
        w0 = p[0]; w1 = p[1];
    }
    __nv_bfloat162 h0 = __floats2bfloat162_rn(w0.x, w0.y);
    __nv_bfloat162 h1 = __floats2bfloat162_rn(w0.z, w0.w);
    __nv_bfloat162 h2 = __floats2bfloat162_rn(w1.x, w1.y);
    __nv_bfloat162 h3 = __floats2bfloat162_rn(w1.z, w1.w);
    uint4 u;
    u.x = *(uint32_t*)&h0; u.y = *(uint32_t*)&h1;
    u.z = *(uint32_t*)&h2; u.w = *(uint32_t*)&h3;
    *(uint4*)&g_Wb[(size_t)rg * DD + kc] = u;
}

// ---------------------------------------------------------------------------
// 4) bf16 mma.sync GEMM + fused softmax partials.
//    CTA: BM=256 rows x BN=128 vocab, K=256 in BK=32 steps, cp.async 2-stage.
//    8 warps in 4x2 grid, warp tile 64x64 (acc[4][8][4] = 128 regs).
// ---------------------------------------------------------------------------
#define BM 256
#define BN 128
#define BK 32
#define PITCH 20                     // uint32 words per smem row (16 + 4 pad)
#define ASTG (BM * PITCH)            // uint32 words per A stage
#define BSTG (BN * PITCH)
#define SMEM_BG ((2*ASTG + 2*BSTG) * 4 + 128*4 + 256*2*4*2)

__device__ __forceinline__ void mma16816(float* c, uint32_t a0, uint32_t a1,
                                         uint32_t a2, uint32_t a3,
                                         uint32_t b0, uint32_t b1) {
    asm volatile("mma.sync.aligned.m16n8k16.row.col.f32.bf16.bf16.f32 "
        "{%0,%1,%2,%3}, {%4,%5,%6,%7}, {%8,%9}, {%0,%1,%2,%3};"
        : "+f"(c[0]), "+f"(c[1]), "+f"(c[2]), "+f"(c[3])
        : "r"(a0), "r"(a1), "r"(a2), "r"(a3), "r"(b0), "r"(b1));
}
__device__ __forceinline__ uint32_t smem_u32(const void* p) {
    uint32_t a;
    asm("{ .reg .u64 t; cvta.to.shared.u64 t, %1; cvt.u32.u64 %0, t; }" : "=r"(a) : "l"(p));
    return a;
}
__device__ __forceinline__ void cp16(uint32_t saddr, const void* gaddr) {
    asm volatile("cp.async.cg.shared.global [%0], [%1], 16;" :: "r"(saddr), "l"(gaddr) : "memory");
}
#define CP_COMMIT() asm volatile("cp.async.commit_group;" ::: "memory")
#define CP_WAIT(n)  asm volatile("cp.async.wait_group %0;" :: "n"(n) : "memory")

__global__ void __launch_bounds__(256, 1) big_gemm_mma(const float* __restrict__ blab) {
    extern __shared__ uint32_t dsm[];
    uint32_t* As = dsm;                       // [2][BM][PITCH]
    uint32_t* Bs = dsm + 2 * ASTG;            // [2][BN][PITCH]
    float* bias_s = (float*)(dsm + 2 * ASTG + 2 * BSTG);      // [128]
    float* pm_s = bias_s + 128;               // [256][2]
    float* ps_s = pm_s + 512;                 // [256][2]

    int tid  = threadIdx.x;
    int wid  = tid >> 5, lane = tid & 31;
    int g    = lane >> 2, t4 = lane & 3;
    int wr   = wid & 3, wc = wid >> 2;        // warp grid 4(m) x 2(n)
    int vt   = blockIdx.x, rt = blockIdx.y;
    int vb   = vt * 128;

    if (tid < 128) {
        int v = vb + tid;
        bias_s[tid] = (v < VV) ? blab[v] : 0.f;
    }

    // cp.async staging: A idx = tid + i*256 (i<4): row=idx>>2, chunk=idx&3
    //                   B idx = tid + i*256 (i<2)
    int arow = tid >> 2, achk = tid & 3;
    const __nv_bfloat16* gA = g_Ab + (size_t)rt * BM * DD;
    const __nv_bfloat16* gB = g_Wb + (size_t)vb * DD;
    uint32_t asb = smem_u32(As);
    uint32_t bsb = smem_u32(Bs);

    float acc[4][8][4] = {};

    // prologue: stage 0 (k0 = 0)
#pragma unroll
    for (int i = 0; i < 4; i++) {
        int row = arow + i * 64;
        cp16(asb + (row * PITCH + achk * 4) * 4, gA + row * DD + achk * 8);
    }
#pragma unroll
    for (int i = 0; i < 2; i++) {
        int row = arow + i * 64;
        cp16(bsb + (row * PITCH + achk * 4) * 4, gB + row * DD + achk * 8);
    }
    CP_COMMIT();

    for (int it = 0; it < 8; it++) {
        int cur = it & 1;
        if (it < 7) {
            int nxt = (it + 1) & 1;
            int k0 = (it + 1) * BK;
#pragma unroll
            for (int i = 0; i < 4; i++) {
                int row = arow + i * 64;
                cp16(asb + (nxt * ASTG + row * PITCH + achk * 4) * 4,
                     gA + row * DD + k0 + achk * 8);
            }
#pragma unroll
            for (int i = 0; i < 2; i++) {
                int row = arow + i * 64;
                cp16(bsb + (nxt * BSTG + row * PITCH + achk * 4) * 4,
                     gB + row * DD + k0 + achk * 8);
            }
            CP_COMMIT();
            CP_WAIT(1);
        } else {
            CP_WAIT(0);
        }
        __syncthreads();

        const uint32_t* Ac = As + cur * ASTG;
        const uint32_t* Bc = Bs + cur * BSTG;
#pragma unroll
        for (int ks = 0; ks < 2; ks++) {
            int w0 = ks * 8 + t4;
            int w1 = w0 + 4;
            uint32_t af[4][4], bf[8][2];
#pragma unroll
            for (int mt = 0; mt < 4; mt++) {
                int m = wr * 64 + mt * 16 + g;
                af[mt][0] = Ac[m * PITCH + w0];
                af[mt][1] = Ac[(m + 8) * PITCH + w0];
                af[mt][2] = Ac[m * PITCH + w1];
                af[mt][3] = Ac[(m + 8) * PITCH + w1];
            }
#pragma unroll
            for (int nt = 0; nt < 8; nt++) {
                int n = wc * 64 + nt * 8 + g;
                bf[nt][0] = Bc[n * PITCH + w0];
                bf[nt][1] = Bc[n * PITCH + w1];
            }
#pragma unroll
            for (int mt = 0; mt < 4; mt++)
#pragma unroll
                for (int nt = 0; nt < 8; nt++)
                    mma16816(acc[mt][nt], af[mt][0], af[mt][1], af[mt][2], af[mt][3],
                             bf[nt][0], bf[nt][1]);
        }
        __syncthreads();
    }

    // --- fused softmax-partial epilogue ---
#pragma unroll
    for (int mt = 0; mt < 4; mt++) {
#pragma unroll
        for (int h = 0; h < 2; h++) {
            int rl = wr * 64 + mt * 16 + h * 8 + g;
            float v[16];
#pragma unroll
            for (int nt = 0; nt < 8; nt++) {
                int col = wc * 64 + nt * 8 + t4 * 2;
                float v0 = acc[mt][nt][h * 2 + 0] + bias_s[col];
                float v1 = acc[mt][nt][h * 2 + 1] + bias_s[col + 1];
                if (vb + col     >= VV) v0 = NEG_BIG;
                if (vb + col + 1 >= VV) v1 = NEG_BIG;
                v[nt * 2 + 0] = v0; v[nt * 2 + 1] = v1;
            }
            float mx = v[0];
#pragma unroll
            for (int j = 1; j < 16; j++) mx = fmaxf(mx, v[j]);
            mx = fmaxf(mx, __shfl_xor_sync(0xffffffffu, mx, 1));
            mx = fmaxf(mx, __shfl_xor_sync(0xffffffffu, mx, 2));
            float s = 0.f;
#pragma unroll
            for (int j = 0; j < 16; j++) s += __expf(v[j] - mx);
            s += __shfl_xor_sync(0xffffffffu, s, 1);
            s += __shfl_xor_sync(0xffffffffu, s, 2);
            if (t4 == 0) { pm_s[rl * 2 + wc] = mx; ps_s[rl * 2 + wc] = s; }
        }
    }
    __syncthreads();
    {
        float m0 = pm_s[tid * 2 + 0], m1 = pm_s[tid * 2 + 1];
        float m = fmaxf(m0, m1);
        float s = ps_s[tid * 2 + 0] * __expf(m0 - m) + ps_s[tid * 2 + 1] * __expf(m1 - m);
        int r = rt * BM + tid;
        g_pm[r * NTV + vt] = m;
        g_ps[r * NTV + vt] = s;
    }
}

// ---------------------------------------------------------------------------
// 5) Per-row reduction: combine partials -> lse, target logit, focal term
// ---------------------------------------------------------------------------
__global__ void row_reduce(const float* __restrict__ Wlab,
                           const float* __restrict__ blab,
                           const int* __restrict__ tags) {
    int warp = (blockIdx.x * blockDim.x + threadIdx.x) >> 5;
    int lane = threadIdx.x & 31;
    if (warp >= NROWS) return;
    int r = warp;
    float m = NEG_BIG, s = 0.f;
    for (int t = lane; t < NTV; t += 32) {
        float mt = g_pm[r * NTV + t];
        float st = g_ps[r * NTV + t];
        if (mt > m) { s = s * __expf(m - mt) + st; m = mt; }
        else        { s += st * __expf(mt - m); }
    }
#pragma unroll
    for (int o = 16; o > 0; o >>= 1) {
        float mo = __shfl_xor_sync(0xffffffffu, m, o);
        float so = __shfl_xor_sync(0xffffffffu, s, o);
        if (mo > m) { s = s * __expf(m - mo) + so; m = mo; }
        else        { s += so * __expf(mo - m); }
    }
    float lse = m + __logf(s);

    int tag = tags[r & (NSPAN - 1)];
    const float* fr = g_feats + r * DD;
    const float* wr = Wlab + (size_t)tag * DD;
    float dot = 0.f;
    for (int d = lane; d < DD; d += 32) dot += fr[d] * wr[d];
#pragma unroll
    for (int o = 16; o > 0; o >>= 1) dot += __shfl_xor_sync(0xffffffffu, dot, o);

    if (lane == 0) {
        float lp = dot + blab[tag] - lse;
        float p = __expf(lp);
        float om = 1.f - p;
        g_focal[r] = -om * om * lp;
    }
}

// ---------------------------------------------------------------------------
// 6) Deterministic final sum
// ---------------------------------------------------------------------------
__global__ void final_reduce(float* __restrict__ out) {
    __shared__ float sm[1024];
    int t = threadIdx.x;
    float s = 0.f;
    for (int i = t; i < NROWS; i += 1024) s += g_focal[i];
    sm[t] = s;
    __syncthreads();
    for (int o = 512; o > 0; o >>= 1) {
        if (t < o) sm[t] += sm[t + o];
        __syncthreads();
    }
    if (t == 0) out[0] = sm[0] / ((float)NROWS + 1e-5f);
}

// ---------------------------------------------------------------------------
extern "C" void kernel_launch(void* const* d_in, const int* in_sizes, int n_in,
                              void* d_out, int out_size) {
    const float* fwd     = (const float*)d_in[0];
    const float* bwd     = (const float*)d_in[1];
    const int*   begins  = (const int*)  d_in[2];
    const int*   ends    = (const int*)  d_in[3];
    const int*   bids    = (const int*)  d_in[4];
    const int*   tags    = (const int*)  d_in[5];
    const float* len_emb = (const float*)d_in[6];
    const float* W_ctx   = (const float*)d_in[7];
    const float* b_ctx   = (const float*)d_in[8];
    const float* W_phr   = (const float*)d_in[9];
    const float* b_phr   = (const float*)d_in[10];
    const float* W_lab   = (const float*)d_in[11];
    const float* b_lab   = (const float*)d_in[12];
    float* out = (float*)d_out;

    cudaFuncSetAttribute(big_gemm_mma, cudaFuncAttributeMaxDynamicSharedMemorySize, SMEM_BG);

    gather_kernel<<<NSPAN, 256>>>(fwd, bwd, begins, ends, bids, len_emb);
    feat_gemm<KC, true ><<<dim3(4, 32), 256>>>(W_ctx, b_ctx, 0);
    feat_gemm<KP, false><<<dim3(4, 32), 256>>>(W_phr, b_phr, NSPAN);
    convert_wlab<<<(NVPAD * 32) / 256, 256>>>(W_lab);
    big_gemm_mma<<<dim3(NTV, 16), 256, SMEM_BG>>>(b_lab);
    row_reduce<<<512, 256>>>(W_lab, b_lab, tags);
    final_reduce<<<1, 1024>>>(out);
}